// round 4
// baseline (speedup 1.0000x reference)
#include <cuda_runtime.h>
#include <cstdint>

#define B 256
#define L 128
#define F 256
#define S 512
#define BF (B*F)
#define G4F 1024

// ---- static device scratch (no allocation) ----
__device__ float g_Wc[G4F * F];     // combined W_ih+W_hh, permuted [nf*128+c][k], tf32-rounded
__device__ float g_WihT[G4F * F];   // [(nf*256+k)*128 + c]  (permuted c)
__device__ float g_WhhT[G4F * F];
__device__ float g_WiT[L * F];      // [k*256 + f]
__device__ float g_bc[G4F];         // permuted combined bias
__device__ float g_init[B * F];
__device__ float g_c1[B * F];

__device__ __forceinline__ float sigf(float x) { return 1.0f / (1.0f + expf(-x)); }
__device__ __forceinline__ float tanhfast(float x) {
    float r; asm("tanh.approx.f32 %0, %1;" : "=f"(r) : "f"(x)); return r;
}
__device__ __forceinline__ float sigfast(float x) { return 0.5f * tanhfast(0.5f * x) + 0.5f; }

// ---- P0: weight prep ----
// col permutation within a 128-col slice: c = (j>>3)*32 + gate*8 + (j&7)
__global__ void prep_kernel(const float* __restrict__ Wih, const float* __restrict__ Whh,
                            const float* __restrict__ bih, const float* __restrict__ bhh,
                            const float* __restrict__ Wi) {
    int bid = blockIdx.x, tid = threadIdx.x;
    if (bid < 1024) {
        int r = bid, k = tid;
        int g = r >> 8;          // gate 0..3 (i,f,g,o)
        int jj = r & 255;        // feature
        int nf = jj >> 5;        // slice
        int j  = jj & 31;
        int c  = ((j >> 3) << 5) + (g << 3) + (j & 7);
        float wih = Wih[r * 256 + k];
        float whh = Whh[r * 256 + k];
        float s = wih + whh;
        unsigned us;
        asm("cvt.rna.tf32.f32 %0, %1;" : "=r"(us) : "f"(s));
        g_Wc[(nf * 128 + c) * 256 + k] = __uint_as_float(us);
        g_WihT[(nf * 256 + k) * 128 + c] = wih;
        g_WhhT[(nf * 256 + k) * 128 + c] = whh;
        if (k == 0) g_bc[nf * 128 + c] = bih[r] + bhh[r];
    } else {
        int k = bid - 1024;      // 0..127
        int f = tid;             // 0..255
        g_WiT[k * 256 + f] = Wi[f * 128 + k];
    }
}

// ---- P1: init = elu(x @ Wi.T + bi), fp32 ----
__global__ void init_kernel(const float* __restrict__ x, const float* __restrict__ bi) {
    __shared__ float xs[32 * 128];
    int bid = blockIdx.x, tid = threadIdx.x;
    int bt = bid >> 2, ft = bid & 3;
    for (int i = tid; i < 32 * 128; i += 256)
        xs[i] = x[(bt * 32 + (i >> 7)) * 128 + (i & 127)];
    __syncthreads();
    int tx = tid & 15, ty = tid >> 4;
    int b0 = ty * 2;
    int f0 = ft * 64 + tx * 4;
    float acc[2][4] = {};
#pragma unroll 4
    for (int k = 0; k < 128; ++k) {
        float4 w = *(const float4*)&g_WiT[k * 256 + f0];
        float x0 = xs[b0 * 128 + k];
        float x1 = xs[(b0 + 1) * 128 + k];
        acc[0][0] += x0 * w.x; acc[0][1] += x0 * w.y; acc[0][2] += x0 * w.z; acc[0][3] += x0 * w.w;
        acc[1][0] += x1 * w.x; acc[1][1] += x1 * w.y; acc[1][2] += x1 * w.z; acc[1][3] += x1 * w.w;
    }
#pragma unroll
    for (int r = 0; r < 2; ++r)
#pragma unroll
        for (int cc = 0; cc < 4; ++cc) {
            float v = acc[r][cc] + bi[f0 + cc];
            v = (v > 0.0f) ? v : expm1f(v);
            g_init[(bt * 32 + b0 + r) * 256 + f0 + cc] = v;
        }
}

// ---- P2: step 0 (inp = last_feat, h = c = init), fp32 ----
__global__ void step0_kernel(const float* __restrict__ lf, float* __restrict__ d_out) {
    extern __shared__ float sm[];
    float* lfs = sm;                 // 4096
    float* ins = lfs + 16 * 256;     // 4096
    float* wih = ins + 16 * 256;     // 8192
    float* whh = wih + 64 * 128;     // 8192
    int tid = threadIdx.x;
    int nf = blockIdx.x & 7, mbt = blockIdx.x >> 3;
    for (int i = tid; i < 16 * 256; i += 256) {
        int gi = (mbt * 16 + (i >> 8)) * 256 + (i & 255);
        lfs[i] = lf[gi];
        ins[i] = g_init[gi];
    }
    int tx = tid & 31, ty = tid >> 5;
    int c0 = tx * 4;
    float acc[2][4] = {};
    for (int kc = 0; kc < 4; ++kc) {
        __syncthreads();
        for (int i = tid; i < 64 * 128; i += 256) {
            int k = kc * 64 + (i >> 7), c = i & 127;
            wih[i] = g_WihT[(nf * 256 + k) * 128 + c];
            whh[i] = g_WhhT[(nf * 256 + k) * 128 + c];
        }
        __syncthreads();
#pragma unroll 4
        for (int k = 0; k < 64; ++k) {
            float4 a4 = *(const float4*)&wih[k * 128 + c0];
            float4 b4 = *(const float4*)&whh[k * 128 + c0];
#pragma unroll
            for (int e = 0; e < 2; ++e) {
                int b = ty + 8 * e;
                float lv = lfs[b * 256 + kc * 64 + k];
                float iv = ins[b * 256 + kc * 64 + k];
                acc[e][0] += lv * a4.x + iv * b4.x;
                acc[e][1] += lv * a4.y + iv * b4.y;
                acc[e][2] += lv * a4.z + iv * b4.z;
                acc[e][3] += lv * a4.w + iv * b4.w;
            }
        }
    }
    __syncthreads();
    float* gss = lfs;  // overlay (lfs dead; ins live)
#pragma unroll
    for (int e = 0; e < 2; ++e)
#pragma unroll
        for (int cc = 0; cc < 4; ++cc)
            gss[(ty + 8 * e) * 132 + c0 + cc] = acc[e][cc];
    __syncthreads();
#pragma unroll
    for (int e2 = 0; e2 < 2; ++e2) {
        int li = tid + 256 * e2;
        int b = li >> 5, j = li & 31;
        int cb = ((j >> 3) << 5) + (j & 7);   // gate 0 col; gates at +8,+16,+24
        float iv = gss[b * 132 + cb]      + g_bc[nf * 128 + cb];
        float fv = gss[b * 132 + cb + 8]  + g_bc[nf * 128 + cb + 8];
        float gv = gss[b * 132 + cb + 16] + g_bc[nf * 128 + cb + 16];
        float ov = gss[b * 132 + cb + 24] + g_bc[nf * 128 + cb + 24];
        float cp = ins[b * 256 + nf * 32 + j];
        float cn = sigf(fv) * cp + sigf(iv) * tanhf(gv);
        float hn = sigf(ov) * tanhf(cn);
        int gi = (mbt * 16 + b) * 256 + nf * 32 + j;
        g_c1[gi] = cn;
        d_out[gi] = hn;   // outs[0] = h_1
    }
}

// ---- tf32 mma helper ----
__device__ __forceinline__ void mma8(float* d, const unsigned* a, unsigned b0, unsigned b1) {
    asm volatile(
        "mma.sync.aligned.m16n8k8.row.col.f32.tf32.tf32.f32 "
        "{%0,%1,%2,%3}, {%4,%5,%6,%7}, {%8,%9}, {%0,%1,%2,%3};"
        : "+f"(d[0]), "+f"(d[1]), "+f"(d[2]), "+f"(d[3])
        : "r"(a[0]), "r"(a[1]), "r"(a[2]), "r"(a[3]), "r"(b0), "r"(b1));
}

// ---- P3: persistent recurrence, t = 1..511 ----
// 128 CTAs x 256 threads, clusters of 8. mb = bid>>3 (16 batch rows), nf = bid&7 (128 gate cols).
// 8 warps = 4 col-groups (32 cols) x 2 k-halves (128 k). Weights in registers.
__global__ void __cluster_dims__(8, 1, 1) __launch_bounds__(256, 1)
lstm_kernel(float* __restrict__ d_out) {
    __shared__ float hs[16 * 260];     // h tile, tf32-rounded, stride 260
    __shared__ float red[128 * 20];    // k-split partials (stride 20: conflict-free .128)

    int tid = threadIdx.x;
    int nf = blockIdx.x & 7, mb = blockIdx.x >> 3;
    int warp = tid >> 5, lane = tid & 31;
    int cg = warp & 3, ks = warp >> 2;
    int gID = lane >> 2, tig = lane & 3;

    // B fragments in registers: warp covers cols [cg*32, cg*32+32), k in [ks*128, ks*128+128)
    unsigned breg[4][16][2];
#pragma unroll
    for (int nt = 0; nt < 4; ++nt)
#pragma unroll
        for (int kb = 0; kb < 16; ++kb) {
            const float* wp = &g_Wc[(nf * 128 + cg * 32 + nt * 8 + gID) * 256 + ks * 128 + kb * 8 + tig];
            breg[nt][kb][0] = __float_as_uint(wp[0]);
            breg[nt][kb][1] = __float_as_uint(wp[4]);
        }

    // bias only in ks=0 accumulators (avoid double add)
    float bias[4][2];
#pragma unroll
    for (int nt = 0; nt < 4; ++nt) {
        float b0 = g_bc[nf * 128 + cg * 32 + nt * 8 + 2 * tig];
        float b1 = g_bc[nf * 128 + cg * 32 + nt * 8 + 2 * tig + 1];
        bias[nt][0] = ks ? 0.0f : b0;
        bias[nt][1] = ks ? 0.0f : b1;
    }

    // cell state (ks=0 threads own cells): q = rh*2+ff -> row gID+rh*8, feat j = cg*8+2tig+ff
    float creg[4];
    if (ks == 0) {
#pragma unroll
        for (int rh = 0; rh < 2; ++rh)
#pragma unroll
            for (int ff = 0; ff < 2; ++ff)
                creg[rh * 2 + ff] =
                    g_c1[(mb * 16 + gID + rh * 8) * 256 + nf * 32 + cg * 8 + 2 * tig + ff];
    }
    __syncthreads();

    for (int t = 1; t < 512; ++t) {
        if (t > 1) asm volatile("barrier.cluster.wait.aligned;" ::: "memory");

        // load h_t (16 x 256) -> smem, tf32-rounded
        const float* hsrc = d_out + (size_t)(t - 1) * BF + (size_t)mb * 4096;
#pragma unroll
        for (int i = tid * 4; i < 4096; i += 1024) {
            float4 v = *(const float4*)(hsrc + i);
            unsigned u0, u1, u2, u3;
            asm("cvt.rna.tf32.f32 %0, %1;" : "=r"(u0) : "f"(v.x));
            asm("cvt.rna.tf32.f32 %0, %1;" : "=r"(u1) : "f"(v.y));
            asm("cvt.rna.tf32.f32 %0, %1;" : "=r"(u2) : "f"(v.z));
            asm("cvt.rna.tf32.f32 %0, %1;" : "=r"(u3) : "f"(v.w));
            v.x = __uint_as_float(u0); v.y = __uint_as_float(u1);
            v.z = __uint_as_float(u2); v.w = __uint_as_float(u3);
            *(float4*)&hs[(i >> 8) * 260 + (i & 255)] = v;
        }
        __syncthreads();

        float acc[4][4];
#pragma unroll
        for (int nt = 0; nt < 4; ++nt) {
            acc[nt][0] = bias[nt][0]; acc[nt][1] = bias[nt][1];
            acc[nt][2] = bias[nt][0]; acc[nt][3] = bias[nt][1];
        }

#pragma unroll
        for (int kb = 0; kb < 16; ++kb) {
            int k0 = ks * 128 + kb * 8;
            unsigned a[4];
            a[0] = __float_as_uint(hs[gID * 260 + k0 + tig]);
            a[1] = __float_as_uint(hs[(gID + 8) * 260 + k0 + tig]);
            a[2] = __float_as_uint(hs[gID * 260 + k0 + 4 + tig]);
            a[3] = __float_as_uint(hs[(gID + 8) * 260 + k0 + 4 + tig]);
#pragma unroll
            for (int nt = 0; nt < 4; ++nt)
                mma8(acc[nt], a, breg[nt][kb][0], breg[nt][kb][1]);
        }

        // k-split reduction: ks=1 warps publish partials
        if (ks == 1) {
            float* rp = &red[(cg * 32 + lane) * 20];
#pragma unroll
            for (int nt = 0; nt < 4; ++nt)
                *(float4*)(rp + nt * 4) = make_float4(acc[nt][0], acc[nt][1], acc[nt][2], acc[nt][3]);
        }
        __syncthreads();

        if (ks == 0) {
            const float* rp = &red[(cg * 32 + lane) * 20];
#pragma unroll
            for (int nt = 0; nt < 4; ++nt) {
                float4 r4 = *(const float4*)(rp + nt * 4);
                acc[nt][0] += r4.x; acc[nt][1] += r4.y;
                acc[nt][2] += r4.z; acc[nt][3] += r4.w;
            }

            // elementwise LSTM + h store
            float* dst = d_out + (size_t)t * BF + (size_t)mb * 4096;
#pragma unroll
            for (int rh = 0; rh < 2; ++rh) {
                float hn2[2];
#pragma unroll
                for (int ff = 0; ff < 2; ++ff) {
                    int q = rh * 2 + ff;
                    float cn = sigfast(acc[1][q]) * creg[q] + sigfast(acc[0][q]) * tanhfast(acc[2][q]);
                    hn2[ff] = sigfast(acc[3][q]) * tanhfast(cn);
                    creg[q] = cn;
                }
                int row = gID + rh * 8;
                *(float2*)(dst + row * 256 + nf * 32 + cg * 8 + 2 * tig) = make_float2(hn2[0], hn2[1]);
            }
        }

        if (t < 511) asm volatile("barrier.cluster.arrive.aligned;" ::: "memory");
    }
}

extern "C" void kernel_launch(void* const* d_in, const int* in_sizes, int n_in,
                              void* d_out, int out_size) {
    const float* x   = (const float*)d_in[0];
    const float* lf  = (const float*)d_in[1];
    const float* Wi  = (const float*)d_in[2];
    const float* bi  = (const float*)d_in[3];
    const float* Wih = (const float*)d_in[4];
    const float* Whh = (const float*)d_in[5];
    const float* bih = (const float*)d_in[6];
    const float* bhh = (const float*)d_in[7];
    float* out = (float*)d_out;

    cudaFuncSetAttribute(step0_kernel, cudaFuncAttributeMaxDynamicSharedMemorySize, 98304);

    prep_kernel<<<1152, 256>>>(Wih, Whh, bih, bhh, Wi);
    init_kernel<<<32, 256>>>(x, bi);
    step0_kernel<<<128, 256, 98304>>>(lf, out);
    lstm_kernel<<<128, 256>>>(out);
}